// round 12
// baseline (speedup 1.0000x reference)
#include <cuda_runtime.h>
#include <cstddef>

#define NX 512
#define NU 32
#define NY 8
#define BB 64
#define TT 512
#define NSTEP 511
#define NPHASE 1022
#define NCTA 128
#define ROWP 516        // padded smem row (floats); 516*4 = 2064 bytes (16B aligned)
#define PREP_CTAS 128

// ---------------- device scratch (sanctioned: __device__ globals) ----------------
__device__ float g_bufA[2 * NX * NX];
__device__ float g_bufB[2 * NX * NX];
__device__ float g_T[2 * NX * NX];
__device__ float g_W0[NX * NX];
__device__ float g_W1[NX * NX];
__device__ float g_Cp[NX * NY];
__device__ float g_inj[(size_t)NSTEP * 2 * BB * NX];   // [t][layer][b][n]
__device__ float g_s0 [(size_t)NSTEP * BB * NX];       // [t][b][n]
__device__ float g_s1 [BB * NX];                       // layer-1 state ping buffer
__device__ int   g_sync[64];                           // [0] = prep barrier counter
// per-CTA phase flags, 16 ints (64B) apart: flag[(g*16+fs)*16]
__device__ int   g_flags[128 * 16];

// ---------------- reset: zero s1 + all sync state ---------------------------------
__global__ void reset_kernel() {
    int idx = blockIdx.x * 256 + threadIdx.x;    // 128*256 = 32768
    g_s1[idx] = 0.0f;
    if (idx < 64) g_sync[idx] = 0;
    if (idx < 128 * 16) g_flags[idx] = 0;
}

// ---------------- prep grid barrier (proven atomic+volatile style) ----------------
__device__ __forceinline__ void gbar(int ph) {
    __syncthreads();
    if (threadIdx.x == 0) {
        __threadfence();
        atomicAdd(&g_sync[0], 1);
        volatile int* cnt = (volatile int*)&g_sync[0];
        while (*cnt < (ph + 1) * PREP_CTAS) { }
        __threadfence();
    }
    __syncthreads();
}

// one 32x32 output tile of a 512^3 GEMM.
// mode 0: C = A@B ; mode 1: C = 2*A - A@B ; mode 2: C = A@B^T
__device__ __forceinline__ void tile_mm(const float* __restrict__ A,
                                        const float* __restrict__ B,
                                        float* __restrict__ C,
                                        int row0, int col0, int mode,
                                        float (*As)[33], float (*Bs)[33]) {
    const int tid = threadIdx.x;
    const int tx = tid & 15, ty = tid >> 4;
    const int lm = tid >> 3;
    const int lk = (tid & 7) * 4;
    float c00 = 0.f, c01 = 0.f, c10 = 0.f, c11 = 0.f;
    for (int k0 = 0; k0 < 512; k0 += 32) {
        float4 a = *(const float4*)&A[(row0 + lm) * 512 + k0 + lk];
        As[lm][lk] = a.x; As[lm][lk+1] = a.y; As[lm][lk+2] = a.z; As[lm][lk+3] = a.w;
        if (mode == 2) {
            float4 b = *(const float4*)&B[(col0 + lm) * 512 + k0 + lk];
            Bs[lk  ][lm] = b.x; Bs[lk+1][lm] = b.y; Bs[lk+2][lm] = b.z; Bs[lk+3][lm] = b.w;
        } else {
            float4 b = *(const float4*)&B[(k0 + lm) * 512 + col0 + lk];
            Bs[lm][lk] = b.x; Bs[lm][lk+1] = b.y; Bs[lm][lk+2] = b.z; Bs[lm][lk+3] = b.w;
        }
        __syncthreads();
#pragma unroll
        for (int kk = 0; kk < 32; ++kk) {
            float a0 = As[ty*2][kk], a1 = As[ty*2+1][kk];
            float b0 = Bs[kk][tx*2], b1 = Bs[kk][tx*2+1];
            c00 = fmaf(a0, b0, c00); c01 = fmaf(a0, b1, c01);
            c10 = fmaf(a1, b0, c10); c11 = fmaf(a1, b1, c11);
        }
        __syncthreads();
    }
    if (mode == 1) {
        c00 = 2.f * A[(row0+ty*2  )*512 + col0+tx*2  ] - c00;
        c01 = 2.f * A[(row0+ty*2  )*512 + col0+tx*2+1] - c01;
        c10 = 2.f * A[(row0+ty*2+1)*512 + col0+tx*2  ] - c10;
        c11 = 2.f * A[(row0+ty*2+1)*512 + col0+tx*2+1] - c11;
    }
    C[(row0+ty*2  )*512 + col0+tx*2  ] = c00;
    C[(row0+ty*2  )*512 + col0+tx*2+1] = c01;
    C[(row0+ty*2+1)*512 + col0+tx*2  ] = c10;
    C[(row0+ty*2+1)*512 + col0+tx*2+1] = c11;
}

// ============== fused prep: Newton-Schulz inverse + W0/W1 + Cp ====================
__global__ void __launch_bounds__(256) prep_kernel(const float* __restrict__ E,
                                                   const float* __restrict__ Hw,
                                                   const float* __restrict__ Cw) {
    __shared__ float As[32][33];
    __shared__ float Bs[32][33];
    const int bid = blockIdx.x, tid = threadIdx.x;

    // phase 0: X0 = 2I - E (both layers)
    {
        int base = (bid * 256 + tid) * 16;
#pragma unroll
        for (int j = 0; j < 16; ++j) {
            int i = base + j;
            int r = (i >> 9) & 511, c = i & 511;
            g_bufA[i] = (r == c ? 2.0f : 0.0f) - E[i];
        }
    }
    gbar(0);

    float* X  = g_bufA;
    float* Xn = g_bufB;
    int ph = 1;
    for (int it = 0; it < 3; ++it) {
        for (int s = 0; s < 4; ++s) {                    // T = E @ X
            int task = bid + s * PREP_CTAS;              // 0..511
            int layer = task >> 8, tr = (task >> 4) & 15, tc = task & 15;
            int off = layer * 262144;
            tile_mm(E + off, X + off, g_T + off, tr * 32, tc * 32, 0, As, Bs);
        }
        gbar(ph++);
        for (int s = 0; s < 4; ++s) {                    // X' = 2X - X@T
            int task = bid + s * PREP_CTAS;
            int layer = task >> 8, tr = (task >> 4) & 15, tc = task & 15;
            int off = layer * 262144;
            tile_mm(X + off, g_T + off, Xn + off, tr * 32, tc * 32, 1, As, Bs);
        }
        gbar(ph++);
        float* sw = X; X = Xn; Xn = sw;
    }
    // final phase: W_l = Einv_l @ Hw_l^T ; Cp = Einv1 @ Cw^T
    for (int s = 0; s < 4; ++s) {
        int task = bid + s * PREP_CTAS;
        int layer = task >> 8, tr = (task >> 4) & 15, tc = task & 15;
        int off = layer * 262144;
        tile_mm(X + off, Hw + off, layer ? g_W1 : g_W0, tr * 32, tc * 32, 2, As, Bs);
    }
    if (bid < 16) {
        const float* Einv1 = X + 262144;
        int m = bid * 32 + (tid >> 3), j = tid & 7;
        float acc = 0.f;
        for (int k = 0; k < 512; ++k)
            acc = fmaf(Einv1[m * 512 + k], Cw[j * 512 + k], acc);
        g_Cp[m * 8 + j] = acc;
    }
}

// ---------------- inj[t][l][b][n] = Hb[l][n] + sum_k u[b][k][t]*Kw[l][n][k] -------
__global__ void __launch_bounds__(256) inj_kernel(const float* __restrict__ u,
                                                  const float* __restrict__ Kw,
                                                  const float* __restrict__ Hb) {
    __shared__ float us[64 * 33];
    __shared__ float kw[64 * 33];
    const int t = blockIdx.x;
    const int l = blockIdx.y >> 3, nb = blockIdx.y & 7;
    const int tid = threadIdx.x;
    for (int i = tid; i < 2048; i += 256) {
        int r = i >> 5, k = i & 31;
        us[r*33 + k] = u[r*16384 + k*512 + t];               // u[b][k][t]
        kw[r*33 + k] = Kw[l*16384 + nb*2048 + i];            // Kw[l][nb*64+r][k]
    }
    __syncthreads();
    const int b = tid >> 2, nq = tid & 3;
    for (int nn = 0; nn < 16; ++nn) {
        int nl = nq * 16 + nn;
        float acc = Hb[l*512 + nb*64 + nl];
#pragma unroll
        for (int k = 0; k < 32; ++k) acc = fmaf(us[b*33+k], kw[nl*33+k], acc);
        g_inj[(((size_t)t*2 + l)*64 + b)*512 + nb*64 + nl] = acc;
    }
}

// ---------------- main persistent recurrence kernel -------------------------------
// 128 CTAs = 8 batch-groups x 16 feature-slices. Weights (both layers) in registers.
// NEW sync: per-CTA phase flags; warp kw waits ONLY on its 2 producers (2kw, 2kw+1),
// stages its 8x64 chunk via L2 (__ldcg), computes immediately (reads only what it
// staged -> __syncwarp suffices). Cross-warp reduce joins all producers' flags
// transitively, which keeps the single s1 ping buffer overwrite-safe.

#define KSLICE_COMPUTE(WP)                                                          \
    _Pragma("unroll")                                                               \
    for (int c = 0; c < 16; ++c) {                                                  \
        _Pragma("unroll")                                                           \
        for (int b = 0; b < 8; ++b) {                                               \
            ulonglong2 sv = *(const ulonglong2*)(ss + b*ROWP + k0 + c*4);           \
            asm("fma.rn.f32x2 %0, %1, %2, %0;" : "+l"(acc[b]) : "l"(sv.x), "l"(WP[2*c]));   \
            asm("fma.rn.f32x2 %0, %1, %2, %0;" : "+l"(acc[b]) : "l"(sv.y), "l"(WP[2*c+1])); \
        }                                                                           \
    }

__global__ void __launch_bounds__(256, 1) main_kernel() {
    __shared__ float ss[8 * ROWP];       // staged activation slab [b][k] (16.5 KB)
    __shared__ float red[8 * 256];       // partials [kw][b*32+f]       (8 KB)
    const int tid = threadIdx.x;
    const int g = blockIdx.x >> 4, fs = blockIdx.x & 15;
    const int nbase = fs * 32, bbase = g * 8;
    const int kw = tid >> 5, lane = tid & 31;
    const int k0 = kw * 64;
    const int fb_b = tid >> 5, fb_f = tid & 31;     // finalize mapping: 8b x 32f

    // ---- load both layers' weight column pairs into registers (once) ----
    unsigned long long wp0[32], wp1[32];
    {
        const int n = nbase + lane;
#pragma unroll
        for (int j = 0; j < 32; ++j) {
            float a0 = g_W0[(k0 + 2*j    )*512 + n];
            float a1 = g_W0[(k0 + 2*j + 1)*512 + n];
            float b0 = g_W1[(k0 + 2*j    )*512 + n];
            float b1 = g_W1[(k0 + 2*j + 1)*512 + n];
            asm("mov.b64 %0, {%1, %2};" : "=l"(wp0[j]) : "f"(a0), "f"(a1));
            asm("mov.b64 %0, {%1, %2};" : "=l"(wp1[j]) : "f"(b0), "f"(b1));
        }
    }
    volatile int* myflag = (volatile int*)&g_flags[(g*16 + fs) * 16];
    volatile int* srcflag = (volatile int*)&g_flags[(g*16 + 2*kw + (lane & 1)) * 16];
    __syncthreads();

    for (int p = 0; p < NPHASE; ++p) {
        const int t = p >> 1, layer = p & 1;
        // inj load hoisted (precomputed; hides DRAM latency under the wait)
        const float injv = __ldg(&g_inj[(((size_t)t*2 + layer)*64 + bbase + fb_b)*512 + nbase + fb_f]);
        // per-warp wait: my 2 producers finished phase p-1 (flag >= p)
        if (lane < 2) {
            while (*srcflag < p) { }
        }
        __syncwarp();
        // stage this warp's 8x64 chunk -> smem (L2-coherent loads)
        const float* sin = layer ? (g_s0 + (size_t)t * 32768) : g_s1;
#pragma unroll
        for (int j = 0; j < 4; ++j) {
            int i = lane + 32 * j;              // 0..127
            int bb = i >> 4, q = i & 15;        // row, float4-quad within 64 cols
            float4 v = __ldcg((const float4*)(sin + (bbase + bb)*512 + k0 + q*4));
            *(float4*)(ss + bb*ROWP + k0 + q*4) = v;
        }
        __syncwarp();
        // ---- per-warp k-slice partial GEMV (weights in regs) ----
        unsigned long long acc[8];
#pragma unroll
        for (int b = 0; b < 8; ++b) acc[b] = 0ull;
        if (layer == 0) { KSLICE_COMPUTE(wp0) } else { KSLICE_COMPUTE(wp1) }
#pragma unroll
        for (int b = 0; b < 8; ++b) {
            float lo, hi;
            asm("mov.b64 {%0, %1}, %2;" : "=f"(lo), "=f"(hi) : "l"(acc[b]));
            red[kw*256 + b*32 + lane] = lo + hi;
        }
        __syncthreads();                       // join: all warps' partials ready
        // ---- reduce 8 k-slices, add inj, relu, store ----
        float sum = injv;
#pragma unroll
        for (int w = 0; w < 8; ++w) sum += red[w*256 + fb_b*32 + fb_f];
        float val = fmaxf(sum, 0.0f);
        float* dst = layer ? g_s1 : (g_s0 + (size_t)t * 32768);
        dst[(bbase + fb_b)*512 + nbase + fb_f] = val;
        __syncthreads();                       // all stores issued before release
        if (tid == 0) {
            __threadfence();
            *myflag = p + 1;                   // release (fence + volatile store)
        }
    }
}

// ---------------- output: y[b][j][t] = s0[t][b][:] @ Cp[:,j] + Cb[j] --------------
__global__ void __launch_bounds__(256) out_kernel(const float* __restrict__ Cb,
                                                  float* __restrict__ y) {
    __shared__ float cp[4096];
    const int t = blockIdx.x, tid = threadIdx.x;
    for (int i = tid; i < 4096; i += 256) cp[i] = g_Cp[i];
    __syncthreads();
    if (t == NSTEP) {   // t == 511: sel row is zero -> y = Cb
        for (int i = tid; i < 512; i += 256)
            y[(i >> 3) * 4096 + (i & 7) * 512 + NSTEP] = Cb[i & 7];
        return;
    }
    const int b = tid >> 2, jp = (tid & 3) * 2;
    const float* srw = g_s0 + (size_t)t * 32768 + b * 512;
    float a0 = Cb[jp], a1 = Cb[jp + 1];
    for (int k = 0; k < 512; k += 4) {
        float4 s = *(const float4*)(srw + k);
        a0 += s.x*cp[k*8+jp]     + s.y*cp[(k+1)*8+jp]     + s.z*cp[(k+2)*8+jp]     + s.w*cp[(k+3)*8+jp];
        a1 += s.x*cp[k*8+jp+1]   + s.y*cp[(k+1)*8+jp+1]   + s.z*cp[(k+2)*8+jp+1]   + s.w*cp[(k+3)*8+jp+1];
    }
    y[b*4096 + jp*512 + t]     = a0;
    y[b*4096 + (jp+1)*512 + t] = a1;
}

// ---------------- host orchestration ----------------------------------------------
extern "C" void kernel_launch(void* const* d_in, const int* in_sizes, int n_in,
                              void* d_out, int out_size) {
    (void)in_sizes; (void)n_in; (void)out_size;
    const float* u  = (const float*)d_in[0];
    const float* E  = (const float*)d_in[1];
    const float* Hw = (const float*)d_in[2];
    const float* Hb = (const float*)d_in[3];
    const float* Kw = (const float*)d_in[4];
    const float* Cw = (const float*)d_in[5];
    const float* Cb = (const float*)d_in[6];
    float* y = (float*)d_out;

    // launch 1: reset sync state + zero s1
    reset_kernel<<<128, 256>>>();
    // launch 2: fused precompute (Newton-Schulz inverse, W0/W1, Cp) @ 128 CTAs
    prep_kernel<<<PREP_CTAS, 256>>>(E, Hw, Cw);
    // launch 3: input injections
    inj_kernel<<<dim3(NSTEP, 16), 256>>>(u, Kw, Hb);
    // launch 4: persistent recurrence (ncu capture slot: 2 harness + 3 mine = skip 5)
    main_kernel<<<NCTA, 256>>>();
    // launch 5: output projection
    out_kernel<<<TT, 256>>>(Cb, y);
}

// round 15
// speedup vs baseline: 1.5156x; 1.5156x over previous
#include <cuda_runtime.h>
#include <cstddef>

#define NX 512
#define NU 32
#define NY 8
#define BB 64
#define TT 512
#define NSTEP 511
#define NPHASE 1022
#define NCTA 128
#define ROWP 516        // padded smem row (floats); 516*4 = 2064 bytes (16B aligned)
#define PREP_CTAS 128

// ---------------- device scratch (sanctioned: __device__ globals) ----------------
__device__ float g_bufA[2 * NX * NX];
__device__ float g_bufB[2 * NX * NX];
__device__ float g_T[2 * NX * NX];
__device__ float g_W0[NX * NX];
__device__ float g_W1[NX * NX];
__device__ float g_Cp[NX * NY];
__device__ float g_inj[(size_t)NSTEP * 2 * BB * NX];   // [t][layer][b][n]
__device__ float g_s0 [(size_t)NSTEP * BB * NX];       // [t][b][n]
__device__ float g_s1 [BB * NX];                       // layer-1 state ping buffer
__device__ int   g_sync[64];                           // [0] = prep barrier counter
// per-CTA phase flags, 16 ints (64B) apart: flag[(g*16+fs)*16]
__device__ int   g_flags[128 * 16];

// ---------------- reset: zero s1 + all sync state ---------------------------------
__global__ void reset_kernel() {
    int idx = blockIdx.x * 256 + threadIdx.x;    // 128*256 = 32768
    g_s1[idx] = 0.0f;
    if (idx < 64) g_sync[idx] = 0;
    if (idx < 128 * 16) g_flags[idx] = 0;
}

// ---------------- prep grid barrier (proven atomic+volatile style) ----------------
__device__ __forceinline__ void gbar(int ph) {
    __syncthreads();
    if (threadIdx.x == 0) {
        __threadfence();
        atomicAdd(&g_sync[0], 1);
        volatile int* cnt = (volatile int*)&g_sync[0];
        while (*cnt < (ph + 1) * PREP_CTAS) { }
        __threadfence();
    }
    __syncthreads();
}

// one 32x32 output tile of a 512^3 GEMM.
// mode 0: C = A@B ; mode 1: C = 2*A - A@B ; mode 2: C = A@B^T
__device__ __forceinline__ void tile_mm(const float* __restrict__ A,
                                        const float* __restrict__ B,
                                        float* __restrict__ C,
                                        int row0, int col0, int mode,
                                        float (*As)[33], float (*Bs)[33]) {
    const int tid = threadIdx.x;
    const int tx = tid & 15, ty = tid >> 4;
    const int lm = tid >> 3;
    const int lk = (tid & 7) * 4;
    float c00 = 0.f, c01 = 0.f, c10 = 0.f, c11 = 0.f;
    for (int k0 = 0; k0 < 512; k0 += 32) {
        float4 a = *(const float4*)&A[(row0 + lm) * 512 + k0 + lk];
        As[lm][lk] = a.x; As[lm][lk+1] = a.y; As[lm][lk+2] = a.z; As[lm][lk+3] = a.w;
        if (mode == 2) {
            float4 b = *(const float4*)&B[(col0 + lm) * 512 + k0 + lk];
            Bs[lk  ][lm] = b.x; Bs[lk+1][lm] = b.y; Bs[lk+2][lm] = b.z; Bs[lk+3][lm] = b.w;
        } else {
            float4 b = *(const float4*)&B[(k0 + lm) * 512 + col0 + lk];
            Bs[lm][lk] = b.x; Bs[lm][lk+1] = b.y; Bs[lm][lk+2] = b.z; Bs[lm][lk+3] = b.w;
        }
        __syncthreads();
#pragma unroll
        for (int kk = 0; kk < 32; ++kk) {
            float a0 = As[ty*2][kk], a1 = As[ty*2+1][kk];
            float b0 = Bs[kk][tx*2], b1 = Bs[kk][tx*2+1];
            c00 = fmaf(a0, b0, c00); c01 = fmaf(a0, b1, c01);
            c10 = fmaf(a1, b0, c10); c11 = fmaf(a1, b1, c11);
        }
        __syncthreads();
    }
    if (mode == 1) {
        c00 = 2.f * A[(row0+ty*2  )*512 + col0+tx*2  ] - c00;
        c01 = 2.f * A[(row0+ty*2  )*512 + col0+tx*2+1] - c01;
        c10 = 2.f * A[(row0+ty*2+1)*512 + col0+tx*2  ] - c10;
        c11 = 2.f * A[(row0+ty*2+1)*512 + col0+tx*2+1] - c11;
    }
    C[(row0+ty*2  )*512 + col0+tx*2  ] = c00;
    C[(row0+ty*2  )*512 + col0+tx*2+1] = c01;
    C[(row0+ty*2+1)*512 + col0+tx*2  ] = c10;
    C[(row0+ty*2+1)*512 + col0+tx*2+1] = c11;
}

// ============== fused prep: Newton-Schulz inverse + W0/W1 + Cp ====================
__global__ void __launch_bounds__(256) prep_kernel(const float* __restrict__ E,
                                                   const float* __restrict__ Hw,
                                                   const float* __restrict__ Cw) {
    __shared__ float As[32][33];
    __shared__ float Bs[32][33];
    const int bid = blockIdx.x, tid = threadIdx.x;

    // phase 0: X0 = 2I - E (both layers)
    {
        int base = (bid * 256 + tid) * 16;
#pragma unroll
        for (int j = 0; j < 16; ++j) {
            int i = base + j;
            int r = (i >> 9) & 511, c = i & 511;
            g_bufA[i] = (r == c ? 2.0f : 0.0f) - E[i];
        }
    }
    gbar(0);

    float* X  = g_bufA;
    float* Xn = g_bufB;
    int ph = 1;
    for (int it = 0; it < 3; ++it) {
        for (int s = 0; s < 4; ++s) {                    // T = E @ X
            int task = bid + s * PREP_CTAS;              // 0..511
            int layer = task >> 8, tr = (task >> 4) & 15, tc = task & 15;
            int off = layer * 262144;
            tile_mm(E + off, X + off, g_T + off, tr * 32, tc * 32, 0, As, Bs);
        }
        gbar(ph++);
        for (int s = 0; s < 4; ++s) {                    // X' = 2X - X@T
            int task = bid + s * PREP_CTAS;
            int layer = task >> 8, tr = (task >> 4) & 15, tc = task & 15;
            int off = layer * 262144;
            tile_mm(X + off, g_T + off, Xn + off, tr * 32, tc * 32, 1, As, Bs);
        }
        gbar(ph++);
        float* sw = X; X = Xn; Xn = sw;
    }
    // final phase: W_l = Einv_l @ Hw_l^T ; Cp = Einv1 @ Cw^T
    for (int s = 0; s < 4; ++s) {
        int task = bid + s * PREP_CTAS;
        int layer = task >> 8, tr = (task >> 4) & 15, tc = task & 15;
        int off = layer * 262144;
        tile_mm(X + off, Hw + off, layer ? g_W1 : g_W0, tr * 32, tc * 32, 2, As, Bs);
    }
    if (bid < 16) {
        const float* Einv1 = X + 262144;
        int m = bid * 32 + (tid >> 3), j = tid & 7;
        float acc = 0.f;
        for (int k = 0; k < 512; ++k)
            acc = fmaf(Einv1[m * 512 + k], Cw[j * 512 + k], acc);
        g_Cp[m * 8 + j] = acc;
    }
}

// ---------------- inj[t][l][b][n] = Hb[l][n] + sum_k u[b][k][t]*Kw[l][n][k] -------
__global__ void __launch_bounds__(256) inj_kernel(const float* __restrict__ u,
                                                  const float* __restrict__ Kw,
                                                  const float* __restrict__ Hb) {
    __shared__ float us[64 * 33];
    __shared__ float kw[64 * 33];
    const int t = blockIdx.x;
    const int l = blockIdx.y >> 3, nb = blockIdx.y & 7;
    const int tid = threadIdx.x;
    for (int i = tid; i < 2048; i += 256) {
        int r = i >> 5, k = i & 31;
        us[r*33 + k] = u[r*16384 + k*512 + t];               // u[b][k][t]
        kw[r*33 + k] = Kw[l*16384 + nb*2048 + i];            // Kw[l][nb*64+r][k]
    }
    __syncthreads();
    const int b = tid >> 2, nq = tid & 3;
    for (int nn = 0; nn < 16; ++nn) {
        int nl = nq * 16 + nn;
        float acc = Hb[l*512 + nb*64 + nl];
#pragma unroll
        for (int k = 0; k < 32; ++k) acc = fmaf(us[b*33+k], kw[nl*33+k], acc);
        g_inj[(((size_t)t*2 + l)*64 + b)*512 + nb*64 + nl] = acc;
    }
}

// ---------------- main persistent recurrence kernel -------------------------------
// 128 CTAs = 8 batch-groups x 16 feature-slices. Weights (both layers) in registers.
// Round-11 skeleton (proven 4429us). Sync changes ONLY:
//  - producers release via fence + volatile store to OWN 64B-strided flag
//    (removes 16-way same-address atomic serialization at L2)
//  - consumers: warp0 lanes poll all 16 flags in parallel (__all_sync ballot),
//    then one threadfence (L1 invalidate -> staging loads see fresh data).

#define KSLICE_COMPUTE(WP)                                                          \
    _Pragma("unroll")                                                               \
    for (int c = 0; c < 16; ++c) {                                                  \
        _Pragma("unroll")                                                           \
        for (int b = 0; b < 8; ++b) {                                               \
            ulonglong2 sv = *(const ulonglong2*)(ss + b*ROWP + k0 + c*4);           \
            asm("fma.rn.f32x2 %0, %1, %2, %0;" : "+l"(acc[b]) : "l"(sv.x), "l"(WP[2*c]));   \
            asm("fma.rn.f32x2 %0, %1, %2, %0;" : "+l"(acc[b]) : "l"(sv.y), "l"(WP[2*c+1])); \
        }                                                                           \
    }

__global__ void __launch_bounds__(256, 1) main_kernel() {
    __shared__ float ss[8 * ROWP];       // staged activation slab [b][k] (16.5 KB)
    __shared__ float red[8 * 256];       // partials [kw][b*32+f]       (8 KB)
    const int tid = threadIdx.x;
    const int g = blockIdx.x >> 4, fs = blockIdx.x & 15;
    const int nbase = fs * 32, bbase = g * 8;
    const int kw = tid >> 5, lane = tid & 31;
    const int k0 = kw * 64;
    const int fb_b = tid >> 5, fb_f = tid & 31;     // finalize mapping: 8b x 32f

    // ---- load both layers' weight column pairs into registers (once) ----
    unsigned long long wp0[32], wp1[32];
    {
        const int n = nbase + lane;
#pragma unroll
        for (int j = 0; j < 32; ++j) {
            float a0 = g_W0[(k0 + 2*j    )*512 + n];
            float a1 = g_W0[(k0 + 2*j + 1)*512 + n];
            float b0 = g_W1[(k0 + 2*j    )*512 + n];
            float b1 = g_W1[(k0 + 2*j + 1)*512 + n];
            asm("mov.b64 %0, {%1, %2};" : "=l"(wp0[j]) : "f"(a0), "f"(a1));
            asm("mov.b64 %0, {%1, %2};" : "=l"(wp1[j]) : "f"(b0), "f"(b1));
        }
    }
    volatile int* myflag   = (volatile int*)&g_flags[(g*16 + fs) * 16];
    volatile int* pollflag = (volatile int*)&g_flags[(g*16 + lane % 16) * 16];
    __syncthreads();

    for (int p = 0; p < NPHASE; ++p) {
        const int t = p >> 1, layer = p & 1;
        // inj load hoisted (precomputed; hides DRAM latency under the wait)
        const float injv = __ldg(&g_inj[(((size_t)t*2 + layer)*64 + bbase + fb_b)*512 + nbase + fb_f]);
        // wait: warp 0 polls all 16 producer flags in parallel
        if (tid < 32) {
            for (;;) {
                int ok = (*pollflag >= p);
                if (__all_sync(0xffffffffu, ok)) break;
            }
            __threadfence();     // L1 invalidate: staging loads must see fresh L2 data
        }
        __syncthreads();
        // stage s_in[8][512] -> smem slab
        const float* sin = layer ? (g_s0 + (size_t)t * 32768) : g_s1;
        for (int i = tid; i < 1024; i += 256) {
            int bb = i >> 7, k4 = (i & 127) << 2;
            *(float4*)(ss + bb*ROWP + k4) = *(const float4*)(sin + (bbase+bb)*512 + k4);
        }
        __syncthreads();
        // ---- per-warp k-slice partial GEMV (weights in regs) ----
        unsigned long long acc[8];
#pragma unroll
        for (int b = 0; b < 8; ++b) acc[b] = 0ull;
        if (layer == 0) { KSLICE_COMPUTE(wp0) } else { KSLICE_COMPUTE(wp1) }
#pragma unroll
        for (int b = 0; b < 8; ++b) {
            float lo, hi;
            asm("mov.b64 {%0, %1}, %2;" : "=f"(lo), "=f"(hi) : "l"(acc[b]));
            red[kw*256 + b*32 + lane] = lo + hi;
        }
        __syncthreads();
        // ---- reduce 8 k-slices, add inj, relu, store ----
        float sum = injv;
#pragma unroll
        for (int w = 0; w < 8; ++w) sum += red[w*256 + fb_b*32 + fb_f];
        float val = fmaxf(sum, 0.0f);
        float* dst = layer ? g_s1 : (g_s0 + (size_t)t * 32768);
        dst[(bbase + fb_b)*512 + nbase + fb_f] = val;
        __syncthreads();                       // all stores issued before release
        if (tid == 0) {
            __threadfence();
            *myflag = p + 1;                   // release: own flag, no atomic
        }
    }
}

// ---------------- output: y[b][j][t] = s0[t][b][:] @ Cp[:,j] + Cb[j] --------------
__global__ void __launch_bounds__(256) out_kernel(const float* __restrict__ Cb,
                                                  float* __restrict__ y) {
    __shared__ float cp[4096];
    const int t = blockIdx.x, tid = threadIdx.x;
    for (int i = tid; i < 4096; i += 256) cp[i] = g_Cp[i];
    __syncthreads();
    if (t == NSTEP) {   // t == 511: sel row is zero -> y = Cb
        for (int i = tid; i < 512; i += 256)
            y[(i >> 3) * 4096 + (i & 7) * 512 + NSTEP] = Cb[i & 7];
        return;
    }
    const int b = tid >> 2, jp = (tid & 3) * 2;
    const float* srw = g_s0 + (size_t)t * 32768 + b * 512;
    float a0 = Cb[jp], a1 = Cb[jp + 1];
    for (int k = 0; k < 512; k += 4) {
        float4 s = *(const float4*)(srw + k);
        a0 += s.x*cp[k*8+jp]     + s.y*cp[(k+1)*8+jp]     + s.z*cp[(k+2)*8+jp]     + s.w*cp[(k+3)*8+jp];
        a1 += s.x*cp[k*8+jp+1]   + s.y*cp[(k+1)*8+jp+1]   + s.z*cp[(k+2)*8+jp+1]   + s.w*cp[(k+3)*8+jp+1];
    }
    y[b*4096 + jp*512 + t]     = a0;
    y[b*4096 + (jp+1)*512 + t] = a1;
}

// ---------------- host orchestration ----------------------------------------------
extern "C" void kernel_launch(void* const* d_in, const int* in_sizes, int n_in,
                              void* d_out, int out_size) {
    (void)in_sizes; (void)n_in; (void)out_size;
    const float* u  = (const float*)d_in[0];
    const float* E  = (const float*)d_in[1];
    const float* Hw = (const float*)d_in[2];
    const float* Hb = (const float*)d_in[3];
    const float* Kw = (const float*)d_in[4];
    const float* Cw = (const float*)d_in[5];
    const float* Cb = (const float*)d_in[6];
    float* y = (float*)d_out;

    // launch 1: reset sync state + zero s1
    reset_kernel<<<128, 256>>>();
    // launch 2: fused precompute (Newton-Schulz inverse, W0/W1, Cp) @ 128 CTAs
    prep_kernel<<<PREP_CTAS, 256>>>(E, Hw, Cw);
    // launch 3: input injections
    inj_kernel<<<dim3(NSTEP, 16), 256>>>(u, Kw, Hb);
    // launch 4: persistent recurrence (ncu capture slot: 2 harness + 3 mine = skip 5)
    main_kernel<<<NCTA, 256>>>();
    // launch 5: output projection
    out_kernel<<<TT, 256>>>(Cb, y);
}

// round 16
// speedup vs baseline: 1.6653x; 1.0988x over previous
#include <cuda_runtime.h>
#include <cstddef>

#define NX 512
#define NU 32
#define NY 8
#define BB 64
#define TT 512
#define NSTEP 511
#define NPHASE 1022
#define NCTA 128
#define ROWP 516        // padded smem row (floats); 516*4 = 2064 bytes (16B aligned)
#define PREP_CTAS 128

// ---------------- device scratch (sanctioned: __device__ globals) ----------------
__device__ float g_bufA[2 * NX * NX];
__device__ float g_bufB[2 * NX * NX];
__device__ float g_T[2 * NX * NX];
__device__ float g_W0[NX * NX];
__device__ float g_W1[NX * NX];
__device__ float g_Cp[NX * NY];
__device__ float g_inj[(size_t)NSTEP * 2 * BB * NX];   // [t][layer][b][n]
__device__ float g_s0 [(size_t)NSTEP * BB * NX];       // [t][b][n]
__device__ float g_s1 [BB * NX];                       // layer-1 state ping buffer
__device__ int   g_sync[64];                           // [0] = prep barrier counter
// per-CTA phase flags, 16 ints (64B) apart: flag[(g*16+fs)*16]
__device__ int   g_flags[128 * 16];

// ---------------- reset: zero s1 + all sync state ---------------------------------
__global__ void reset_kernel() {
    int idx = blockIdx.x * 256 + threadIdx.x;    // 128*256 = 32768
    g_s1[idx] = 0.0f;
    if (idx < 64) g_sync[idx] = 0;
    if (idx < 128 * 16) g_flags[idx] = 0;
}

// ---------------- prep grid barrier (proven atomic+volatile style) ----------------
__device__ __forceinline__ void gbar(int ph) {
    __syncthreads();
    if (threadIdx.x == 0) {
        __threadfence();
        atomicAdd(&g_sync[0], 1);
        volatile int* cnt = (volatile int*)&g_sync[0];
        while (*cnt < (ph + 1) * PREP_CTAS) { }
        __threadfence();
    }
    __syncthreads();
}

// one 32x32 output tile of a 512^3 GEMM.
// mode 0: C = A@B ; mode 1: C = 2*A - A@B ; mode 2: C = A@B^T
__device__ __forceinline__ void tile_mm(const float* __restrict__ A,
                                        const float* __restrict__ B,
                                        float* __restrict__ C,
                                        int row0, int col0, int mode,
                                        float (*As)[33], float (*Bs)[33]) {
    const int tid = threadIdx.x;
    const int tx = tid & 15, ty = tid >> 4;
    const int lm = tid >> 3;
    const int lk = (tid & 7) * 4;
    float c00 = 0.f, c01 = 0.f, c10 = 0.f, c11 = 0.f;
    for (int k0 = 0; k0 < 512; k0 += 32) {
        float4 a = *(const float4*)&A[(row0 + lm) * 512 + k0 + lk];
        As[lm][lk] = a.x; As[lm][lk+1] = a.y; As[lm][lk+2] = a.z; As[lm][lk+3] = a.w;
        if (mode == 2) {
            float4 b = *(const float4*)&B[(col0 + lm) * 512 + k0 + lk];
            Bs[lk  ][lm] = b.x; Bs[lk+1][lm] = b.y; Bs[lk+2][lm] = b.z; Bs[lk+3][lm] = b.w;
        } else {
            float4 b = *(const float4*)&B[(k0 + lm) * 512 + col0 + lk];
            Bs[lm][lk] = b.x; Bs[lm][lk+1] = b.y; Bs[lm][lk+2] = b.z; Bs[lm][lk+3] = b.w;
        }
        __syncthreads();
#pragma unroll
        for (int kk = 0; kk < 32; ++kk) {
            float a0 = As[ty*2][kk], a1 = As[ty*2+1][kk];
            float b0 = Bs[kk][tx*2], b1 = Bs[kk][tx*2+1];
            c00 = fmaf(a0, b0, c00); c01 = fmaf(a0, b1, c01);
            c10 = fmaf(a1, b0, c10); c11 = fmaf(a1, b1, c11);
        }
        __syncthreads();
    }
    if (mode == 1) {
        c00 = 2.f * A[(row0+ty*2  )*512 + col0+tx*2  ] - c00;
        c01 = 2.f * A[(row0+ty*2  )*512 + col0+tx*2+1] - c01;
        c10 = 2.f * A[(row0+ty*2+1)*512 + col0+tx*2  ] - c10;
        c11 = 2.f * A[(row0+ty*2+1)*512 + col0+tx*2+1] - c11;
    }
    C[(row0+ty*2  )*512 + col0+tx*2  ] = c00;
    C[(row0+ty*2  )*512 + col0+tx*2+1] = c01;
    C[(row0+ty*2+1)*512 + col0+tx*2  ] = c10;
    C[(row0+ty*2+1)*512 + col0+tx*2+1] = c11;
}

// ============== fused prep: Newton-Schulz inverse + W0/W1 + Cp ====================
__global__ void __launch_bounds__(256) prep_kernel(const float* __restrict__ E,
                                                   const float* __restrict__ Hw,
                                                   const float* __restrict__ Cw) {
    __shared__ float As[32][33];
    __shared__ float Bs[32][33];
    const int bid = blockIdx.x, tid = threadIdx.x;

    // phase 0: X0 = 2I - E (both layers)
    {
        int base = (bid * 256 + tid) * 16;
#pragma unroll
        for (int j = 0; j < 16; ++j) {
            int i = base + j;
            int r = (i >> 9) & 511, c = i & 511;
            g_bufA[i] = (r == c ? 2.0f : 0.0f) - E[i];
        }
    }
    gbar(0);

    float* X  = g_bufA;
    float* Xn = g_bufB;
    int ph = 1;
    for (int it = 0; it < 3; ++it) {
        for (int s = 0; s < 4; ++s) {                    // T = E @ X
            int task = bid + s * PREP_CTAS;              // 0..511
            int layer = task >> 8, tr = (task >> 4) & 15, tc = task & 15;
            int off = layer * 262144;
            tile_mm(E + off, X + off, g_T + off, tr * 32, tc * 32, 0, As, Bs);
        }
        gbar(ph++);
        for (int s = 0; s < 4; ++s) {                    // X' = 2X - X@T
            int task = bid + s * PREP_CTAS;
            int layer = task >> 8, tr = (task >> 4) & 15, tc = task & 15;
            int off = layer * 262144;
            tile_mm(X + off, g_T + off, Xn + off, tr * 32, tc * 32, 1, As, Bs);
        }
        gbar(ph++);
        float* sw = X; X = Xn; Xn = sw;
    }
    // final phase: W_l = Einv_l @ Hw_l^T ; Cp = Einv1 @ Cw^T
    for (int s = 0; s < 4; ++s) {
        int task = bid + s * PREP_CTAS;
        int layer = task >> 8, tr = (task >> 4) & 15, tc = task & 15;
        int off = layer * 262144;
        tile_mm(X + off, Hw + off, layer ? g_W1 : g_W0, tr * 32, tc * 32, 2, As, Bs);
    }
    if (bid < 16) {
        const float* Einv1 = X + 262144;
        int m = bid * 32 + (tid >> 3), j = tid & 7;
        float acc = 0.f;
        for (int k = 0; k < 512; ++k)
            acc = fmaf(Einv1[m * 512 + k], Cw[j * 512 + k], acc);
        g_Cp[m * 8 + j] = acc;
    }
}

// ---------------- inj[t][l][b][n] = Hb[l][n] + sum_k u[b][k][t]*Kw[l][n][k] -------
__global__ void __launch_bounds__(256) inj_kernel(const float* __restrict__ u,
                                                  const float* __restrict__ Kw,
                                                  const float* __restrict__ Hb) {
    __shared__ float us[64 * 33];
    __shared__ float kw[64 * 33];
    const int t = blockIdx.x;
    const int l = blockIdx.y >> 3, nb = blockIdx.y & 7;
    const int tid = threadIdx.x;
    for (int i = tid; i < 2048; i += 256) {
        int r = i >> 5, k = i & 31;
        us[r*33 + k] = u[r*16384 + k*512 + t];               // u[b][k][t]
        kw[r*33 + k] = Kw[l*16384 + nb*2048 + i];            // Kw[l][nb*64+r][k]
    }
    __syncthreads();
    const int b = tid >> 2, nq = tid & 3;
    for (int nn = 0; nn < 16; ++nn) {
        int nl = nq * 16 + nn;
        float acc = Hb[l*512 + nb*64 + nl];
#pragma unroll
        for (int k = 0; k < 32; ++k) acc = fmaf(us[b*33+k], kw[nl*33+k], acc);
        g_inj[(((size_t)t*2 + l)*64 + b)*512 + nb*64 + nl] = acc;
    }
}

// ---------------- main persistent recurrence kernel -------------------------------
// 128 CTAs = 8 batch-groups x 16 feature-slices. 512 threads = 16 warps.
// Warp w owns k-slice [32w, 32w+32); lane = output feature. Per-thread weights
// drop to 64 regs (both layers), freeing registers for LDS pipelining and giving
// 4 warps/SMSP for latency hiding. Sync: proven round-15 flag protocol.

#define KSLICE_COMPUTE(WP)                                                          \
    _Pragma("unroll")                                                               \
    for (int c = 0; c < 8; ++c) {                                                   \
        _Pragma("unroll")                                                           \
        for (int b = 0; b < 8; ++b) {                                               \
            ulonglong2 sv = *(const ulonglong2*)(ss + b*ROWP + k0 + c*4);           \
            asm("fma.rn.f32x2 %0, %1, %2, %0;" : "+l"(acc[b]) : "l"(sv.x), "l"(WP[2*c]));   \
            asm("fma.rn.f32x2 %0, %1, %2, %0;" : "+l"(acc[b]) : "l"(sv.y), "l"(WP[2*c+1])); \
        }                                                                           \
    }

__global__ void __launch_bounds__(512, 1) main_kernel() {
    __shared__ float ss[8 * ROWP];       // staged activation slab [b][k] (16.5 KB)
    __shared__ float red[16 * 256];      // partials [kw][b*32+f]        (16 KB)
    const int tid = threadIdx.x;
    const int g = blockIdx.x >> 4, fs = blockIdx.x & 15;
    const int nbase = fs * 32, bbase = g * 8;
    const int kw = tid >> 5, lane = tid & 31;
    const int k0 = kw * 32;
    const int fb_b = (tid >> 5) & 7, fb_f = tid & 31;   // finalize mapping (tid<256)

    // ---- load both layers' weight column pairs into registers (once) ----
    // warp kw covers k in [32kw, 32kw+32): 16 f32x2 pairs per layer
    unsigned long long wp0[16], wp1[16];
    {
        const int n = nbase + lane;
#pragma unroll
        for (int j = 0; j < 16; ++j) {
            float a0 = g_W0[(k0 + 2*j    )*512 + n];
            float a1 = g_W0[(k0 + 2*j + 1)*512 + n];
            float b0 = g_W1[(k0 + 2*j    )*512 + n];
            float b1 = g_W1[(k0 + 2*j + 1)*512 + n];
            asm("mov.b64 %0, {%1, %2};" : "=l"(wp0[j]) : "f"(a0), "f"(a1));
            asm("mov.b64 %0, {%1, %2};" : "=l"(wp1[j]) : "f"(b0), "f"(b1));
        }
    }
    volatile int* myflag   = (volatile int*)&g_flags[(g*16 + fs) * 16];
    volatile int* pollflag = (volatile int*)&g_flags[(g*16 + (lane & 15)) * 16];
    __syncthreads();

    for (int p = 0; p < NPHASE; ++p) {
        const int t = p >> 1, layer = p & 1;
        // inj load hoisted (precomputed; hides DRAM latency under the wait)
        float injv = 0.0f;
        if (tid < 256)
            injv = __ldg(&g_inj[(((size_t)t*2 + layer)*64 + bbase + fb_b)*512 + nbase + fb_f]);
        // wait: warp 0 polls all 16 producer flags in parallel
        if (tid < 32) {
            for (;;) {
                int ok = (*pollflag >= p);
                if (__all_sync(0xffffffffu, ok)) break;
            }
            __threadfence();     // L1 invalidate: staging loads must see fresh L2 data
        }
        __syncthreads();
        // stage s_in[8][512] -> smem slab (1024 float4 over 512 threads)
        const float* sin = layer ? (g_s0 + (size_t)t * 32768) : g_s1;
        {
            int i0 = tid, i1 = tid + 512;
            int bb0 = i0 >> 7, k40 = (i0 & 127) << 2;
            int bb1 = i1 >> 7, k41 = (i1 & 127) << 2;
            *(float4*)(ss + bb0*ROWP + k40) = *(const float4*)(sin + (bbase+bb0)*512 + k40);
            *(float4*)(ss + bb1*ROWP + k41) = *(const float4*)(sin + (bbase+bb1)*512 + k41);
        }
        __syncthreads();
        // ---- per-warp k-slice partial GEMV (weights in regs) ----
        unsigned long long acc[8];
#pragma unroll
        for (int b = 0; b < 8; ++b) acc[b] = 0ull;
        if (layer == 0) { KSLICE_COMPUTE(wp0) } else { KSLICE_COMPUTE(wp1) }
#pragma unroll
        for (int b = 0; b < 8; ++b) {
            float lo, hi;
            asm("mov.b64 {%0, %1}, %2;" : "=f"(lo), "=f"(hi) : "l"(acc[b]));
            red[kw*256 + b*32 + lane] = lo + hi;
        }
        __syncthreads();
        // ---- reduce 16 k-slices, add inj, relu, store (threads 0..255) ----
        if (tid < 256) {
            float sum = injv;
#pragma unroll
            for (int w = 0; w < 16; ++w) sum += red[w*256 + fb_b*32 + fb_f];
            float val = fmaxf(sum, 0.0f);
            float* dst = layer ? g_s1 : (g_s0 + (size_t)t * 32768);
            dst[(bbase + fb_b)*512 + nbase + fb_f] = val;
        }
        __syncthreads();                       // all stores issued before release
        if (tid == 0) {
            __threadfence();
            *myflag = p + 1;                   // release: own flag, no atomic
        }
    }
}

// ---------------- output: y[b][j][t] = s0[t][b][:] @ Cp[:,j] + Cb[j] --------------
__global__ void __launch_bounds__(256) out_kernel(const float* __restrict__ Cb,
                                                  float* __restrict__ y) {
    __shared__ float cp[4096];
    const int t = blockIdx.x, tid = threadIdx.x;
    for (int i = tid; i < 4096; i += 256) cp[i] = g_Cp[i];
    __syncthreads();
    if (t == NSTEP) {   // t == 511: sel row is zero -> y = Cb
        for (int i = tid; i < 512; i += 256)
            y[(i >> 3) * 4096 + (i & 7) * 512 + NSTEP] = Cb[i & 7];
        return;
    }
    const int b = tid >> 2, jp = (tid & 3) * 2;
    const float* srw = g_s0 + (size_t)t * 32768 + b * 512;
    float a0 = Cb[jp], a1 = Cb[jp + 1];
    for (int k = 0; k < 512; k += 4) {
        float4 s = *(const float4*)(srw + k);
        a0 += s.x*cp[k*8+jp]     + s.y*cp[(k+1)*8+jp]     + s.z*cp[(k+2)*8+jp]     + s.w*cp[(k+3)*8+jp];
        a1 += s.x*cp[k*8+jp+1]   + s.y*cp[(k+1)*8+jp+1]   + s.z*cp[(k+2)*8+jp+1]   + s.w*cp[(k+3)*8+jp+1];
    }
    y[b*4096 + jp*512 + t]     = a0;
    y[b*4096 + (jp+1)*512 + t] = a1;
}

// ---------------- host orchestration ----------------------------------------------
extern "C" void kernel_launch(void* const* d_in, const int* in_sizes, int n_in,
                              void* d_out, int out_size) {
    (void)in_sizes; (void)n_in; (void)out_size;
    const float* u  = (const float*)d_in[0];
    const float* E  = (const float*)d_in[1];
    const float* Hw = (const float*)d_in[2];
    const float* Hb = (const float*)d_in[3];
    const float* Kw = (const float*)d_in[4];
    const float* Cw = (const float*)d_in[5];
    const float* Cb = (const float*)d_in[6];
    float* y = (float*)d_out;

    // launch 1: reset sync state + zero s1
    reset_kernel<<<128, 256>>>();
    // launch 2: fused precompute (Newton-Schulz inverse, W0/W1, Cp) @ 128 CTAs
    prep_kernel<<<PREP_CTAS, 256>>>(E, Hw, Cw);
    // launch 3: input injections
    inj_kernel<<<dim3(NSTEP, 16), 256>>>(u, Kw, Hb);
    // launch 4: persistent recurrence (ncu capture slot: 2 harness + 3 mine = skip 5)
    main_kernel<<<NCTA, 512>>>();
    // launch 5: output projection
    out_kernel<<<TT, 256>>>(Cb, y);
}